// round 2
// baseline (speedup 1.0000x reference)
#include <cuda_runtime.h>

#define BATCH 2
#define NSEQ  2048
#define DIMM  1024
#define NH    8
#define DH    64
#define NE    8
#define TTOK  (BATCH*NSEQ)     /* 4096 tokens */
#define BH    (BATCH*NH)       /* 16 */
#define GCOLS (NH*NE)          /* 64 gate columns */
#define PROJN (2*NH*DH + GCOLS) /* 1088 */

// ---------------- scratch (static device globals; allowed) ----------------
static __device__ float g_q[BH*NSEQ*DH];          // (b,h,n,d)
static __device__ float g_k[BH*NSEQ*DH];
static __device__ float g_glogit[TTOK*GCOLS];     // raw gate logits, (t, h*8+e)
static __device__ float g_gate[BH*NSEQ];          // selected sigmoid gate, (b,h,n)
static __device__ int   g_cnt[NH*NE];             // bucket counts
static __device__ int   g_list[NH*NE*TTOK];       // token ids per (h,e) bucket
static __device__ float g_vals[BH*NSEQ*DH];       // gated value projections
static __device__ float g_attn[BH*NSEQ*DH];       // attention output
static __device__ float g_outh[(size_t)BH*NSEQ*DIMM]; // per-head output (128MB)

// ---------------- init: zero bucket counters ----------------
__global__ void init_kernel() {
    int i = threadIdx.x;
    if (i < NH*NE) g_cnt[i] = 0;
}

// ---------------- kernel 1: fused QK+gate projection GEMM ----------------
// X(4096x1024) @ [Wq | Wk | Wgate](1024x1088). 64x64 tile, 256 thr, 4x4 micro.
__global__ void __launch_bounds__(256, 2)
proj_kernel(const float* __restrict__ x,
            const float* __restrict__ wq,
            const float* __restrict__ wk,
            const float* __restrict__ wg) {
    __shared__ float As[16][68];   // [k][m]
    __shared__ float Bs[16][68];   // [k][c]
    int tid = threadIdx.x;
    int bm = blockIdx.x, bn = blockIdx.y;
    int tr = tid >> 4, tc = tid & 15;
    float acc[4][4] = {};

    for (int k0 = 0; k0 < DIMM; k0 += 16) {
#pragma unroll
        for (int r = 0; r < 4; r++) {
            int e = tid + 256*r;
            int m = e >> 4, kk = e & 15;
            As[kk][m] = x[(size_t)(bm*64 + m)*DIMM + k0 + kk];
            int col = e & 63, k2 = e >> 6;
            int c = bn*64 + col;
            int krow = k0 + k2;
            float w;
            if      (c < 512)  w = wq[(size_t)krow*512 + c];
            else if (c < 1024) w = wk[(size_t)krow*512 + (c - 512)];
            else               w = wg[(size_t)krow*64  + (c - 1024)];
            Bs[k2][col] = w;
        }
        __syncthreads();
#pragma unroll
        for (int kk = 0; kk < 16; kk++) {
            float4 a4 = *(const float4*)&As[kk][tr*4];
            float4 b4 = *(const float4*)&Bs[kk][tc*4];
            float av[4] = {a4.x, a4.y, a4.z, a4.w};
            float bv[4] = {b4.x, b4.y, b4.z, b4.w};
#pragma unroll
            for (int i = 0; i < 4; i++)
#pragma unroll
                for (int j = 0; j < 4; j++)
                    acc[i][j] += av[i] * bv[j];
        }
        __syncthreads();
    }
#pragma unroll
    for (int i = 0; i < 4; i++) {
        int row = bm*64 + tr*4 + i;
        int b_ = row / NSEQ, n = row % NSEQ;
#pragma unroll
        for (int j = 0; j < 4; j++) {
            int c = bn*64 + tc*4 + j;
            float v = acc[i][j];
            if (c < 512) {
                g_q[((size_t)(b_*NH + (c >> 6))*NSEQ + n)*DH + (c & 63)] = v;
            } else if (c < 1024) {
                int c2 = c - 512;
                g_k[((size_t)(b_*NH + (c2 >> 6))*NSEQ + n)*DH + (c2 & 63)] = v;
            } else {
                g_glogit[(size_t)row*GCOLS + (c - 1024)] = v;
            }
        }
    }
}

// ---------------- kernel 2: gate sigmoid + argmax + bucket append ----------------
__global__ void gate_kernel() {
    int id = blockIdx.x * blockDim.x + threadIdx.x;
    if (id >= TTOK*NH) return;
    int t = id / NH, h = id % NH;
    const float* lg = &g_glogit[(size_t)t*GCOLS + h*NE];
    float best = lg[0]; int be = 0;
#pragma unroll
    for (int e = 1; e < NE; e++) { float v = lg[e]; if (v > best) { best = v; be = e; } }
    float gate = 1.f / (1.f + __expf(-best));
    int b_ = t / NSEQ, n = t % NSEQ;
    g_gate[(size_t)(b_*NH + h)*NSEQ + n] = gate;
    int pos = atomicAdd(&g_cnt[h*NE + be], 1);
    g_list[(size_t)(h*NE + be)*TTOK + pos] = t;
}

// ---------------- kernel 3: grouped value-expert GEMM ----------------
// per (h,e) bucket: gather X rows (tok x 1024) @ W_eh (1024x64), scale by gate
__global__ void __launch_bounds__(256, 2)
value_kernel(const float* __restrict__ x,
             const float* __restrict__ vexp) {
    __shared__ float As[16][68];
    __shared__ float Bs[16][68];
    __shared__ int   ts[64];
    __shared__ float gts[64];
    int he = blockIdx.x; int h = he / NE, e = he % NE;
    int cnt = g_cnt[he];
    int start = blockIdx.y * 64;
    if (start >= cnt) return;
    int tid = threadIdx.x;
    if (tid < 64) {
        int t = (start + tid < cnt) ? g_list[(size_t)he*TTOK + start + tid] : -1;
        ts[tid] = t;
        gts[tid] = (t >= 0) ? g_gate[(size_t)((t/NSEQ)*NH + h)*NSEQ + (t % NSEQ)] : 0.f;
    }
    __syncthreads();
    const float* W = vexp + (size_t)(e*NH + h)*DIMM*DH;
    int tr = tid >> 4, tc = tid & 15;
    float acc[4][4] = {};
    for (int k0 = 0; k0 < DIMM; k0 += 16) {
#pragma unroll
        for (int r = 0; r < 4; r++) {
            int e_ = tid + 256*r;
            int m = e_ >> 4, kk = e_ & 15;
            int t = ts[m];
            As[kk][m] = (t >= 0) ? x[(size_t)t*DIMM + k0 + kk] : 0.f;
            int col = e_ & 63, k2 = e_ >> 6;
            Bs[k2][col] = W[(size_t)(k0 + k2)*DH + col];
        }
        __syncthreads();
#pragma unroll
        for (int kk = 0; kk < 16; kk++) {
            float4 a4 = *(const float4*)&As[kk][tr*4];
            float4 b4 = *(const float4*)&Bs[kk][tc*4];
            float av[4] = {a4.x, a4.y, a4.z, a4.w};
            float bv[4] = {b4.x, b4.y, b4.z, b4.w};
#pragma unroll
            for (int i = 0; i < 4; i++)
#pragma unroll
                for (int j = 0; j < 4; j++)
                    acc[i][j] += av[i] * bv[j];
        }
        __syncthreads();
    }
#pragma unroll
    for (int i = 0; i < 4; i++) {
        int m = tr*4 + i;
        int t = ts[m];
        if (t < 0) continue;
        float g = gts[m];
        size_t base = ((size_t)(t/NSEQ)*NH + h)*NSEQ + (t % NSEQ);
#pragma unroll
        for (int j = 0; j < 4; j++)
            g_vals[base*DH + tc*4 + j] = g * acc[i][j];
    }
}

// ---------------- kernel 4: causal flash attention (fp32) ----------------
#define SMS 68
#define ATTN_SMEM ((4*64*SMS + 3*64) * 4)
__global__ void __launch_bounds__(256, 2)
attn_kernel() {
    extern __shared__ float sm[];
    float* Qs = sm;                 // [d][m]
    float* Ks = Qs + 64*SMS;        // [d][j]
    float* Vs = Ks + 64*SMS;        // [j][d]
    float* Ps = Vs + 64*SMS;        // [m][j]
    float* m_s = Ps + 64*SMS;
    float* l_s = m_s + 64;
    float* f_s = l_s + 64;
    int bh = blockIdx.x, qt = blockIdx.y;
    int qbase = qt * 64;
    int tid = threadIdx.x, tr = tid >> 4, tc = tid & 15;
    const float scale = 0.125f;     // DH^-0.5

#pragma unroll
    for (int r = 0; r < 16; r++) {
        int e = tid + 256*r;
        int d = e & 63, m = e >> 6;
        Qs[d*SMS + m] = g_q[((size_t)bh*NSEQ + qbase + m)*DH + d] * scale;
    }
    if (tid < 64) { m_s[tid] = -1e30f; l_s[tid] = 0.f; }
    float o[4][4] = {};

    for (int jt = 0; jt <= qt; jt++) {
        __syncthreads();
#pragma unroll
        for (int r = 0; r < 16; r++) {
            int e = tid + 256*r;
            int d = e & 63, j = e >> 6;
            Ks[d*SMS + j] = g_k[((size_t)bh*NSEQ + jt*64 + j)*DH + d];
            Vs[j*SMS + d] = g_vals[((size_t)bh*NSEQ + jt*64 + j)*DH + d];
        }
        __syncthreads();
        float s[4][4] = {};
#pragma unroll 8
        for (int d = 0; d < 64; d++) {
            float4 a4 = *(const float4*)&Qs[d*SMS + tr*4];
            float4 b4 = *(const float4*)&Ks[d*SMS + tc*4];
            float av[4] = {a4.x, a4.y, a4.z, a4.w};
            float bv[4] = {b4.x, b4.y, b4.z, b4.w};
#pragma unroll
            for (int i = 0; i < 4; i++)
#pragma unroll
                for (int j = 0; j < 4; j++)
                    s[i][j] += av[i] * bv[j];
        }
        if (jt == qt) {
#pragma unroll
            for (int i = 0; i < 4; i++)
#pragma unroll
                for (int j = 0; j < 4; j++)
                    if (jt*64 + tc*4 + j > qbase + tr*4 + i) s[i][j] = -1e30f;
        }
#pragma unroll
        for (int i = 0; i < 4; i++)
#pragma unroll
            for (int j = 0; j < 4; j++)
                Ps[(tr*4 + i)*SMS + tc*4 + j] = s[i][j];
        __syncthreads();
        if (tid < 64) {
            float* P = &Ps[tid*SMS];
            float mo = m_s[tid];
            float mx = mo;
#pragma unroll 8
            for (int j = 0; j < 64; j++) mx = fmaxf(mx, P[j]);
            float f = __expf(mo - mx);
            float sum = 0.f;
#pragma unroll 8
            for (int j = 0; j < 64; j++) { float p = __expf(P[j] - mx); P[j] = p; sum += p; }
            m_s[tid] = mx;
            l_s[tid] = l_s[tid]*f + sum;
            f_s[tid] = f;
        }
        __syncthreads();
        float fi[4];
#pragma unroll
        for (int i = 0; i < 4; i++) fi[i] = f_s[tr*4 + i];
#pragma unroll
        for (int i = 0; i < 4; i++)
#pragma unroll
            for (int j = 0; j < 4; j++)
                o[i][j] *= fi[i];
#pragma unroll 8
        for (int j = 0; j < 64; j++) {
            float4 b4 = *(const float4*)&Vs[j*SMS + tc*4];
            float bv[4] = {b4.x, b4.y, b4.z, b4.w};
            float av[4];
#pragma unroll
            for (int i = 0; i < 4; i++) av[i] = Ps[(tr*4 + i)*SMS + j];
#pragma unroll
            for (int i = 0; i < 4; i++)
#pragma unroll
                for (int jj = 0; jj < 4; jj++)
                    o[i][jj] += av[i] * bv[jj];
        }
    }
#pragma unroll
    for (int i = 0; i < 4; i++) {
        float inv = 1.f / l_s[tr*4 + i];
#pragma unroll
        for (int j = 0; j < 4; j++)
            g_attn[((size_t)bh*NSEQ + qbase + tr*4 + i)*DH + tc*4 + j] = o[i][j] * inv;
    }
}

// ---------------- kernel 5: grouped output-expert GEMM ----------------
// per (h,e) bucket: (gate * attn_out)(tok x 64) @ W_eh (64x1024) -> g_outh
__global__ void __launch_bounds__(256, 2)
output_kernel(const float* __restrict__ oexp) {
    __shared__ float As[64][68];   // [k][m]
    __shared__ float Bs[64][68];   // [k][c]
    __shared__ int   ts[64];
    __shared__ float gts[64];
    int he = blockIdx.x; int h = he / NE, e = he % NE;
    int cnt = g_cnt[he];
    int start = blockIdx.y * 64;
    if (start >= cnt) return;
    int ct = blockIdx.z;           // 0..15 column tiles
    int tid = threadIdx.x;
    if (tid < 64) {
        int t = (start + tid < cnt) ? g_list[(size_t)he*TTOK + start + tid] : -1;
        ts[tid] = t;
        gts[tid] = (t >= 0) ? g_gate[(size_t)((t/NSEQ)*NH + h)*NSEQ + (t % NSEQ)] : 0.f;
    }
    __syncthreads();
#pragma unroll
    for (int r = 0; r < 16; r++) {
        int e_ = tid + 256*r;
        int k = e_ & 63, m = e_ >> 6;
        int t = ts[m];
        As[k][m] = (t >= 0)
            ? g_attn[((size_t)((t/NSEQ)*NH + h)*NSEQ + (t % NSEQ))*DH + k] * gts[m]
            : 0.f;
    }
    const float* W = oexp + (size_t)(e*NH + h)*DH*DIMM;
#pragma unroll
    for (int r = 0; r < 16; r++) {
        int e_ = tid + 256*r;
        int c = e_ & 63, k = e_ >> 6;
        Bs[k][c] = W[(size_t)k*DIMM + ct*64 + c];
    }
    __syncthreads();
    int tr = tid >> 4, tc = tid & 15;
    float acc[4][4] = {};
#pragma unroll 8
    for (int k = 0; k < 64; k++) {
        float4 a4 = *(const float4*)&As[k][tr*4];
        float4 b4 = *(const float4*)&Bs[k][tc*4];
        float av[4] = {a4.x, a4.y, a4.z, a4.w};
        float bv[4] = {b4.x, b4.y, b4.z, b4.w};
#pragma unroll
        for (int i = 0; i < 4; i++)
#pragma unroll
            for (int j = 0; j < 4; j++)
                acc[i][j] += av[i] * bv[j];
    }
#pragma unroll
    for (int i = 0; i < 4; i++) {
        int m = tr*4 + i;
        int t = ts[m];
        if (t < 0) continue;
        size_t base = ((size_t)(t/NSEQ)*NH + h)*NSEQ + (t % NSEQ);
#pragma unroll
        for (int j = 0; j < 4; j++)
            g_outh[base*DIMM + ct*64 + tc*4 + j] = acc[i][j];
    }
}

// ---------------- kernel 6: sum over heads ----------------
__global__ void reduce_kernel(float* __restrict__ out) {
    int idx = blockIdx.x * blockDim.x + threadIdx.x;
    const int total = TTOK * (DIMM/4);
    const float4* ph = (const float4*)g_outh;
    float4* po = (float4*)out;
    for (; idx < total; idx += gridDim.x * blockDim.x) {
        int t = idx >> 8;          // DIMM/4 = 256
        int d4 = idx & 255;
        int b_ = t / NSEQ, n = t % NSEQ;
        float4 s = make_float4(0.f, 0.f, 0.f, 0.f);
#pragma unroll
        for (int h = 0; h < NH; h++) {
            float4 v = ph[((size_t)(b_*NH + h)*NSEQ + n)*256 + d4];
            s.x += v.x; s.y += v.y; s.z += v.z; s.w += v.w;
        }
        po[idx] = s;
    }
}

// ---------------- launch ----------------
extern "C" void kernel_launch(void* const* d_in, const int* in_sizes, int n_in,
                              void* d_out, int out_size) {
    const float* x  = (const float*)d_in[0];
    const float* wq = (const float*)d_in[1];
    const float* wk = (const float*)d_in[2];
    const float* wg = (const float*)d_in[3];
    const float* ve = (const float*)d_in[4];
    const float* oe = (const float*)d_in[5];
    float* out = (float*)d_out;

    cudaFuncSetAttribute(attn_kernel,
                         cudaFuncAttributeMaxDynamicSharedMemorySize, ATTN_SMEM);

    init_kernel<<<1, 64>>>();
    proj_kernel<<<dim3(64, 17), 256>>>(x, wq, wk, wg);
    gate_kernel<<<(TTOK*NH)/256, 256>>>();
    value_kernel<<<dim3(NH*NE, TTOK/64), 256>>>(x, ve);
    attn_kernel<<<dim3(BH, NSEQ/64), 256, ATTN_SMEM>>>();
    output_kernel<<<dim3(NH*NE, TTOK/64, DIMM/64), 256>>>(oe);
    reduce_kernel<<<2048, 256>>>(out);
}

// round 3
// speedup vs baseline: 1.5753x; 1.5753x over previous
#include <cuda_runtime.h>

#define BATCH 2
#define NSEQ  2048
#define DIMM  1024
#define NH    8
#define DH    64
#define NE    8
#define TTOK  (BATCH*NSEQ)     /* 4096 tokens */
#define BH    (BATCH*NH)       /* 16 */
#define GCOLS (NH*NE)          /* 64 gate columns */

// ---------------- scratch (static device globals; allowed) ----------------
static __device__ float g_q[BH*NSEQ*DH];
static __device__ float g_k[BH*NSEQ*DH];
static __device__ float g_glogit[TTOK*GCOLS];
static __device__ float g_gate[BH*NSEQ];
static __device__ int   g_cnt[NH*NE];
static __device__ int   g_list[NH*NE*TTOK];
static __device__ float g_vals[BH*NSEQ*DH];
static __device__ float g_attn[BH*NSEQ*DH];
static __device__ float g_outh[(size_t)BH*NSEQ*DIMM];

__global__ void init_kernel() {
    int i = threadIdx.x;
    if (i < NH*NE) g_cnt[i] = 0;
}

// ---------------- kernel 1: fused QK+gate projection GEMM ----------------
// X(4096x1024) @ [Wq|Wk|Wgate](1024x1088). 128x128 tile, 256 thr, 8x8 micro,
// double-buffered K-chunks of 8.
__global__ void __launch_bounds__(256, 2)
proj_kernel(const float* __restrict__ x,
            const float* __restrict__ wq,
            const float* __restrict__ wk,
            const float* __restrict__ wg) {
    __shared__ float As[2][8][128];   // [k][m]
    __shared__ float Bs[2][8][128];   // [k][n]
    int tid = threadIdx.x;
    int bm = blockIdx.x, bn = blockIdx.y;

    int la_row = tid >> 1;            // 0..127
    int la_k   = (tid & 1) * 4;       // 0 | 4
    const float* aptr = x + (size_t)(bm*128 + la_row)*DIMM + la_k;

    int lb_k = tid >> 5;              // 0..7
    int lb_n = (tid & 31) * 4;        // 0..124
    int gc   = bn*128 + lb_n;         // global col (float4 never straddles segs)

    int tyy = tid >> 4, txx = tid & 15;
    float acc[8][8] = {};
    float4 pa, pb;

    // prologue: chunk 0
    pa = *(const float4*)(aptr + 0);
    {
        int krow = lb_k;
        if (gc < 512)       pb = *(const float4*)&wq[(size_t)krow*512 + gc];
        else if (gc < 1024) pb = *(const float4*)&wk[(size_t)krow*512 + gc - 512];
        else if (gc < 1088) pb = *(const float4*)&wg[(size_t)krow*64  + gc - 1024];
        else                pb = make_float4(0.f,0.f,0.f,0.f);
    }
    As[0][la_k+0][la_row] = pa.x; As[0][la_k+1][la_row] = pa.y;
    As[0][la_k+2][la_row] = pa.z; As[0][la_k+3][la_row] = pa.w;
    *(float4*)&Bs[0][lb_k][lb_n] = pb;
    __syncthreads();

    const int NC = DIMM/8;  // 128 chunks
    for (int c = 0; c < NC; c++) {
        int cur = c & 1;
        if (c + 1 < NC) {
            int k0 = (c + 1) * 8;
            pa = *(const float4*)(aptr + k0);
            int krow = k0 + lb_k;
            if (gc < 512)       pb = *(const float4*)&wq[(size_t)krow*512 + gc];
            else if (gc < 1024) pb = *(const float4*)&wk[(size_t)krow*512 + gc - 512];
            else if (gc < 1088) pb = *(const float4*)&wg[(size_t)krow*64  + gc - 1024];
            else                pb = make_float4(0.f,0.f,0.f,0.f);
        }
#pragma unroll
        for (int kk = 0; kk < 8; kk++) {
            float4 a0 = *(const float4*)&As[cur][kk][tyy*8];
            float4 a1 = *(const float4*)&As[cur][kk][tyy*8+4];
            float4 b0 = *(const float4*)&Bs[cur][kk][txx*8];
            float4 b1 = *(const float4*)&Bs[cur][kk][txx*8+4];
            float av[8] = {a0.x,a0.y,a0.z,a0.w,a1.x,a1.y,a1.z,a1.w};
            float bv[8] = {b0.x,b0.y,b0.z,b0.w,b1.x,b1.y,b1.z,b1.w};
#pragma unroll
            for (int i = 0; i < 8; i++)
#pragma unroll
                for (int j = 0; j < 8; j++)
                    acc[i][j] += av[i] * bv[j];
        }
        if (c + 1 < NC) {
            int nxt = cur ^ 1;
            __syncthreads();
            As[nxt][la_k+0][la_row] = pa.x; As[nxt][la_k+1][la_row] = pa.y;
            As[nxt][la_k+2][la_row] = pa.z; As[nxt][la_k+3][la_row] = pa.w;
            *(float4*)&Bs[nxt][lb_k][lb_n] = pb;
            __syncthreads();
        }
    }
#pragma unroll
    for (int i = 0; i < 8; i++) {
        int row = bm*128 + tyy*8 + i;
        int b_ = row >> 11, n = row & 2047;
#pragma unroll
        for (int j = 0; j < 8; j++) {
            int c = bn*128 + txx*8 + j;
            float v = acc[i][j];
            if (c < 512) {
                g_q[((size_t)(b_*NH + (c >> 6))*NSEQ + n)*DH + (c & 63)] = v;
            } else if (c < 1024) {
                int c2 = c - 512;
                g_k[((size_t)(b_*NH + (c2 >> 6))*NSEQ + n)*DH + (c2 & 63)] = v;
            } else if (c < 1088) {
                g_glogit[(size_t)row*GCOLS + (c - 1024)] = v;
            }
        }
    }
}

// ---------------- kernel 2: gate sigmoid + argmax + bucket append ----------------
__global__ void gate_kernel() {
    int id = blockIdx.x * blockDim.x + threadIdx.x;
    if (id >= TTOK*NH) return;
    int t = id / NH, h = id % NH;
    const float* lg = &g_glogit[(size_t)t*GCOLS + h*NE];
    float best = lg[0]; int be = 0;
#pragma unroll
    for (int e = 1; e < NE; e++) { float v = lg[e]; if (v > best) { best = v; be = e; } }
    float gate = 1.f / (1.f + __expf(-best));
    int b_ = t >> 11, n = t & 2047;
    g_gate[(size_t)(b_*NH + h)*NSEQ + n] = gate;
    int pos = atomicAdd(&g_cnt[h*NE + be], 1);
    g_list[(size_t)(h*NE + be)*TTOK + pos] = t;
}

// ---------------- kernel 3: grouped value-expert GEMM ----------------
// per (h,e) bucket: gather X(tok x 1024) @ W_eh(1024x64), scale by gate.
// 128x64 tile, 128 thr, 8x8 micro, double-buffered K-chunks of 8.
__global__ void __launch_bounds__(128, 4)
value_kernel(const float* __restrict__ x,
             const float* __restrict__ vexp) {
    __shared__ float As[2][8][128];
    __shared__ float Bs[2][8][64];
    __shared__ int   ts[128];
    __shared__ float gts[128];
    int he = blockIdx.x; int h = he >> 3, e = he & 7;
    int cnt = g_cnt[he];
    int start = blockIdx.y * 128;
    if (start >= cnt) return;
    int tid = threadIdx.x;
    {
        int t = (start + tid < cnt) ? g_list[(size_t)he*TTOK + start + tid] : -1;
        ts[tid] = t;
        gts[tid] = (t >= 0) ? g_gate[(size_t)((t>>11)*NH + h)*NSEQ + (t & 2047)] : 0.f;
    }
    __syncthreads();
    const float* W = vexp + (size_t)(e*NH + h)*DIMM*DH;
    int at = ts[tid];
    const float* aptr = x + (size_t)(at >= 0 ? at : 0)*DIMM;
    int lb_k = tid >> 4, lb_n = (tid & 15) * 4;
    int tyy = tid >> 3, txx = tid & 7;
    float acc[8][8] = {};
    float4 pa0, pa1, pb;

    // prologue chunk 0
    if (at >= 0) { pa0 = *(const float4*)(aptr + 0); pa1 = *(const float4*)(aptr + 4); }
    else { pa0 = pa1 = make_float4(0.f,0.f,0.f,0.f); }
    pb = *(const float4*)&W[(size_t)lb_k*DH + lb_n];
    As[0][0][tid]=pa0.x; As[0][1][tid]=pa0.y; As[0][2][tid]=pa0.z; As[0][3][tid]=pa0.w;
    As[0][4][tid]=pa1.x; As[0][5][tid]=pa1.y; As[0][6][tid]=pa1.z; As[0][7][tid]=pa1.w;
    *(float4*)&Bs[0][lb_k][lb_n] = pb;
    __syncthreads();

    const int NC = DIMM/8;
    for (int c = 0; c < NC; c++) {
        int cur = c & 1;
        if (c + 1 < NC) {
            int k0 = (c + 1) * 8;
            if (at >= 0) { pa0 = *(const float4*)(aptr + k0); pa1 = *(const float4*)(aptr + k0 + 4); }
            else { pa0 = pa1 = make_float4(0.f,0.f,0.f,0.f); }
            pb = *(const float4*)&W[(size_t)(k0 + lb_k)*DH + lb_n];
        }
#pragma unroll
        for (int kk = 0; kk < 8; kk++) {
            float4 a0 = *(const float4*)&As[cur][kk][tyy*8];
            float4 a1 = *(const float4*)&As[cur][kk][tyy*8+4];
            float4 b0 = *(const float4*)&Bs[cur][kk][txx*8];
            float4 b1 = *(const float4*)&Bs[cur][kk][txx*8+4];
            float av[8] = {a0.x,a0.y,a0.z,a0.w,a1.x,a1.y,a1.z,a1.w};
            float bv[8] = {b0.x,b0.y,b0.z,b0.w,b1.x,b1.y,b1.z,b1.w};
#pragma unroll
            for (int i = 0; i < 8; i++)
#pragma unroll
                for (int j = 0; j < 8; j++)
                    acc[i][j] += av[i] * bv[j];
        }
        if (c + 1 < NC) {
            int nxt = cur ^ 1;
            __syncthreads();
            As[nxt][0][tid]=pa0.x; As[nxt][1][tid]=pa0.y; As[nxt][2][tid]=pa0.z; As[nxt][3][tid]=pa0.w;
            As[nxt][4][tid]=pa1.x; As[nxt][5][tid]=pa1.y; As[nxt][6][tid]=pa1.z; As[nxt][7][tid]=pa1.w;
            *(float4*)&Bs[nxt][lb_k][lb_n] = pb;
            __syncthreads();
        }
    }
#pragma unroll
    for (int i = 0; i < 8; i++) {
        int m = tyy*8 + i;
        int t = ts[m];
        if (t < 0) continue;
        float g = gts[m];
        size_t base = ((size_t)(t>>11)*NH + h)*NSEQ + (t & 2047);
        float4 v0 = make_float4(acc[i][0]*g, acc[i][1]*g, acc[i][2]*g, acc[i][3]*g);
        float4 v1 = make_float4(acc[i][4]*g, acc[i][5]*g, acc[i][6]*g, acc[i][7]*g);
        *(float4*)&g_vals[base*DH + txx*8]     = v0;
        *(float4*)&g_vals[base*DH + txx*8 + 4] = v1;
    }
}

// ---------------- kernel 4: causal flash attention (fp32) ----------------
// q-tile 128, kv-tile 64, 256 threads, 8x4 micro, softmax across all threads.
#define QP 132
#define KP 68
#define ATTN_SMEM ((64*QP + 64*KP + 64*KP + 128*KP + 3*128) * 4)
__global__ void __launch_bounds__(256, 1)
attn_kernel() {
    extern __shared__ float sm[];
    float* Qs = sm;                  // [d][m] pitch QP
    float* Ks = Qs + 64*QP;          // [d][j] pitch KP
    float* Vs = Ks + 64*KP;          // [j][d] pitch KP
    float* Ps = Vs + 64*KP;          // [m][j] pitch KP
    float* m_s = Ps + 128*KP;
    float* l_s = m_s + 128;
    float* f_s = l_s + 128;
    int bh = blockIdx.x;
    int qt = (int)(gridDim.y - 1) - (int)blockIdx.y;  // heavy tiles first
    int qbase = qt * 128;
    int tid = threadIdx.x;
    int tyy = tid >> 4, txx = tid & 15;
    const float scale = 0.125f;

#pragma unroll
    for (int r = 0; r < 8; r++) {
        int id = tid + 256*r;
        int m = id >> 4, d4 = (id & 15) * 4;
        float4 v = *(const float4*)&g_q[((size_t)bh*NSEQ + qbase + m)*DH + d4];
        Qs[(d4+0)*QP + m] = v.x * scale;
        Qs[(d4+1)*QP + m] = v.y * scale;
        Qs[(d4+2)*QP + m] = v.z * scale;
        Qs[(d4+3)*QP + m] = v.w * scale;
    }
    if (tid < 128) { m_s[tid] = -1e30f; l_s[tid] = 0.f; }
    float o[8][4] = {};

    int ntiles = qt*2 + 2;
    for (int jt = 0; jt < ntiles; jt++) {
        __syncthreads();
#pragma unroll
        for (int r = 0; r < 4; r++) {
            int id = tid + 256*r;
            int j = id >> 4, d4 = (id & 15) * 4;
            float4 kv = *(const float4*)&g_k[((size_t)bh*NSEQ + jt*64 + j)*DH + d4];
            Ks[(d4+0)*KP + j] = kv.x;
            Ks[(d4+1)*KP + j] = kv.y;
            Ks[(d4+2)*KP + j] = kv.z;
            Ks[(d4+3)*KP + j] = kv.w;
            float4 vv = *(const float4*)&g_vals[((size_t)bh*NSEQ + jt*64 + j)*DH + d4];
            *(float4*)&Vs[j*KP + d4] = vv;
        }
        __syncthreads();
        float s[8][4] = {};
#pragma unroll 8
        for (int d = 0; d < 64; d++) {
            float4 a0 = *(const float4*)&Qs[d*QP + tyy*8];
            float4 a1 = *(const float4*)&Qs[d*QP + tyy*8 + 4];
            float4 b  = *(const float4*)&Ks[d*KP + txx*4];
            float av[8] = {a0.x,a0.y,a0.z,a0.w,a1.x,a1.y,a1.z,a1.w};
            float bv[4] = {b.x,b.y,b.z,b.w};
#pragma unroll
            for (int i = 0; i < 8; i++)
#pragma unroll
                for (int j = 0; j < 4; j++)
                    s[i][j] += av[i] * bv[j];
        }
        // causal mask (only tiles that can touch the diagonal)
        if (jt*64 + 63 > qbase + tyy*8) {
#pragma unroll
            for (int i = 0; i < 8; i++)
#pragma unroll
                for (int j = 0; j < 4; j++)
                    if (jt*64 + txx*4 + j > qbase + tyy*8 + i) s[i][j] = -1e30f;
        }
#pragma unroll
        for (int i = 0; i < 8; i++)
            *(float4*)&Ps[(tyy*8+i)*KP + txx*4] =
                make_float4(s[i][0], s[i][1], s[i][2], s[i][3]);
        __syncthreads();
        // online softmax: 2 threads per row
        {
            int row = tid >> 1, half = tid & 1;
            float* P = &Ps[row*KP + half*32];
            float mx = m_s[row];
#pragma unroll 8
            for (int j2 = 0; j2 < 32; j2++) mx = fmaxf(mx, P[j2]);
            mx = fmaxf(mx, __shfl_xor_sync(0xffffffffu, mx, 1));
            float sum = 0.f;
#pragma unroll 8
            for (int j2 = 0; j2 < 32; j2++) {
                float p = __expf(P[j2] - mx); P[j2] = p; sum += p;
            }
            sum += __shfl_xor_sync(0xffffffffu, sum, 1);
            if (half == 0) {
                float mo = m_s[row];
                float f = __expf(mo - mx);
                m_s[row] = mx;
                l_s[row] = l_s[row]*f + sum;
                f_s[row] = f;
            }
        }
        __syncthreads();
        float fr[8];
#pragma unroll
        for (int i = 0; i < 8; i++) fr[i] = f_s[tyy*8 + i];
#pragma unroll
        for (int i = 0; i < 8; i++)
#pragma unroll
            for (int j = 0; j < 4; j++)
                o[i][j] *= fr[i];
#pragma unroll 8
        for (int jj = 0; jj < 64; jj++) {
            float4 b = *(const float4*)&Vs[jj*KP + txx*4];
            float bv[4] = {b.x,b.y,b.z,b.w};
#pragma unroll
            for (int i = 0; i < 8; i++) {
                float a = Ps[(tyy*8+i)*KP + jj];
#pragma unroll
                for (int j = 0; j < 4; j++)
                    o[i][j] += a * bv[j];
            }
        }
    }
#pragma unroll
    for (int i = 0; i < 8; i++) {
        int row = tyy*8 + i;
        float inv = 1.f / l_s[row];
        float4 ov = make_float4(o[i][0]*inv, o[i][1]*inv, o[i][2]*inv, o[i][3]*inv);
        *(float4*)&g_attn[((size_t)bh*NSEQ + qbase + row)*DH + txx*4] = ov;
    }
}

// ---------------- kernel 5: grouped output-expert GEMM ----------------
// per (h,e) bucket: (gate*attn)(tok x 64) @ W_eh(64x1024) -> g_outh.
// 128x128 tile, K=64 in 16-chunks, 256 thr, 8x8 micro.
__global__ void __launch_bounds__(256, 2)
output_kernel(const float* __restrict__ oexp) {
    __shared__ float As[16][128];
    __shared__ float Bs[16][128];
    __shared__ int   ts[128];
    __shared__ float gts[128];
    int he = blockIdx.x; int h = he >> 3, e = he & 7;
    int cnt = g_cnt[he];
    int start = blockIdx.y * 128;
    if (start >= cnt) return;
    int ct = blockIdx.z;   // 0..7 (128-col tiles)
    int tid = threadIdx.x;
    if (tid < 128) {
        int t = (start + tid < cnt) ? g_list[(size_t)he*TTOK + start + tid] : -1;
        ts[tid] = t;
        gts[tid] = (t >= 0) ? g_gate[(size_t)((t>>11)*NH + h)*NSEQ + (t & 2047)] : 0.f;
    }
    __syncthreads();
    const float* W = oexp + (size_t)(e*NH + h)*DH*DIMM + ct*128;
    int tyy = tid >> 4, txx = tid & 15;
    float acc[8][8] = {};
    for (int k0 = 0; k0 < DH; k0 += 16) {
        if (k0) __syncthreads();
#pragma unroll
        for (int r = 0; r < 2; r++) {
            int id = tid + 256*r;
            int row = id >> 2, kq = (id & 3) * 4;
            int t = ts[row];
            float4 v = make_float4(0.f,0.f,0.f,0.f);
            if (t >= 0) {
                size_t base = ((size_t)(t>>11)*NH + h)*NSEQ + (t & 2047);
                v = *(const float4*)&g_attn[base*DH + k0 + kq];
                float g = gts[row];
                v.x *= g; v.y *= g; v.z *= g; v.w *= g;
            }
            As[kq+0][row] = v.x; As[kq+1][row] = v.y;
            As[kq+2][row] = v.z; As[kq+3][row] = v.w;
        }
#pragma unroll
        for (int r = 0; r < 2; r++) {
            int id = tid + 256*r;
            int k = id >> 5, n4 = (id & 31) * 4;
            *(float4*)&Bs[k][n4] = *(const float4*)&W[(size_t)(k0 + k)*DIMM + n4];
        }
        __syncthreads();
#pragma unroll
        for (int kk = 0; kk < 16; kk++) {
            float4 a0 = *(const float4*)&As[kk][tyy*8];
            float4 a1 = *(const float4*)&As[kk][tyy*8+4];
            float4 b0 = *(const float4*)&Bs[kk][txx*8];
            float4 b1 = *(const float4*)&Bs[kk][txx*8+4];
            float av[8] = {a0.x,a0.y,a0.z,a0.w,a1.x,a1.y,a1.z,a1.w};
            float bv[8] = {b0.x,b0.y,b0.z,b0.w,b1.x,b1.y,b1.z,b1.w};
#pragma unroll
            for (int i = 0; i < 8; i++)
#pragma unroll
                for (int j = 0; j < 8; j++)
                    acc[i][j] += av[i] * bv[j];
        }
    }
#pragma unroll
    for (int i = 0; i < 8; i++) {
        int m = tyy*8 + i;
        int t = ts[m];
        if (t < 0) continue;
        size_t base = ((size_t)(t>>11)*NH + h)*NSEQ + (t & 2047);
        float* dst = &g_outh[base*DIMM + ct*128 + txx*8];
        *(float4*)dst       = make_float4(acc[i][0], acc[i][1], acc[i][2], acc[i][3]);
        *(float4*)(dst + 4) = make_float4(acc[i][4], acc[i][5], acc[i][6], acc[i][7]);
    }
}

// ---------------- kernel 6: sum over heads ----------------
__global__ void reduce_kernel(float* __restrict__ out) {
    int idx = blockIdx.x * blockDim.x + threadIdx.x;
    const int total = TTOK * (DIMM/4);
    const float4* ph = (const float4*)g_outh;
    float4* po = (float4*)out;
    for (; idx < total; idx += gridDim.x * blockDim.x) {
        int t = idx >> 8;
        int d4 = idx & 255;
        int b_ = t >> 11, n = t & 2047;
        float4 s = make_float4(0.f,0.f,0.f,0.f);
#pragma unroll
        for (int h = 0; h < NH; h++) {
            float4 v = ph[((size_t)(b_*NH + h)*NSEQ + n)*256 + d4];
            s.x += v.x; s.y += v.y; s.z += v.z; s.w += v.w;
        }
        po[idx] = s;
    }
}

// ---------------- launch ----------------
extern "C" void kernel_launch(void* const* d_in, const int* in_sizes, int n_in,
                              void* d_out, int out_size) {
    const float* x  = (const float*)d_in[0];
    const float* wq = (const float*)d_in[1];
    const float* wk = (const float*)d_in[2];
    const float* wg = (const float*)d_in[3];
    const float* ve = (const float*)d_in[4];
    const float* oe = (const float*)d_in[5];
    float* out = (float*)d_out;

    cudaFuncSetAttribute(attn_kernel,
                         cudaFuncAttributeMaxDynamicSharedMemorySize, ATTN_SMEM);

    init_kernel<<<1, 64>>>();
    proj_kernel<<<dim3(32, 9), 256>>>(x, wq, wk, wg);
    gate_kernel<<<(TTOK*NH)/256, 256>>>();
    value_kernel<<<dim3(NH*NE, TTOK/128), 128>>>(x, ve);
    attn_kernel<<<dim3(BH, NSEQ/128), 256, ATTN_SMEM>>>();
    output_kernel<<<dim3(NH*NE, TTOK/128, DIMM/128), 256>>>(oe);
    reduce_kernel<<<2048, 256>>>(out);
}